// round 2
// baseline (speedup 1.0000x reference)
#include <cuda_runtime.h>

// ---------------- constants ----------------
#define SC 0.70710678118654752f

// qshift polyphase filter tables (7 taps each; see analysis)
__constant__ float cG0B_E[7] = { 0.00325314f,  0.03466035f, -0.11720389f,  0.75614564f,  0.01186609f,  0.02382538f, -0.00543948f};
__constant__ float cG0B_O[7] = {-0.00388321f, -0.03887280f,  0.27529538f,  0.56881042f, -0.10671180f,  0.01702522f, -0.00455690f};
__constant__ float cG0A_E[7] = {-0.00455690f,  0.01702522f, -0.10671180f,  0.56881042f,  0.27529538f, -0.03887280f, -0.00388321f};
__constant__ float cG0A_O[7] = {-0.00543948f,  0.02382538f,  0.01186609f,  0.75614564f, -0.11720389f,  0.03466035f,  0.00325314f};
__constant__ float cG1B_E[7] = {-0.00455690f,  0.01702522f, -0.10671180f,  0.56881042f,  0.27529538f, -0.03887280f, -0.00388321f};
__constant__ float cG1B_O[7] = { 0.00543948f, -0.02382538f, -0.01186609f, -0.75614564f,  0.11720389f, -0.03466035f, -0.00325314f};
__constant__ float cG1A_E[7] = {-0.00325314f, -0.03466035f,  0.11720389f, -0.75614564f, -0.01186609f, -0.02382538f,  0.00543948f};
__constant__ float cG1A_O[7] = {-0.00388321f, -0.03887280f,  0.27529538f,  0.56881042f, -0.10671180f,  0.01702522f, -0.00455690f};

// biort synthesis filters
__constant__ float cG0O[7] = {-0.0107142857142857f, -0.0535714285714286f, 0.2607142857142857f,
                               0.6071428571428571f,  0.2607142857142857f, -0.0535714285714286f,
                              -0.0107142857142857f};
__constant__ float cG1O[5] = {-0.05f, -0.25f, 0.6f, -0.25f, -0.05f};

// ---------------- scratch (device globals; no allocation) ----------------
// y1,y2: (8,512,256,3); Z,t1,t2: (8,512,512,3)
__device__ float g_y1[8 * 512 * 256 * 3];
__device__ float g_y2[8 * 512 * 256 * 3];
__device__ float g_Z [8 * 512 * 512 * 3];
__device__ float g_t1[8 * 512 * 512 * 3];
__device__ float g_t2[8 * 512 * 512 * 3];

// ---------------- helpers ----------------
__device__ __forceinline__ int refl(int x, int L) {
    x = (x < 0) ? (-1 - x) : x;
    return (x >= L) ? (2 * L - 1 - x) : x;
}

// c2q on the fly: value of the quad-image subband (pair sa,sb) at (r,k) for channel c.
// hi is a (B, HW, HW, 36) tensor; the subband image is (2*HW, 2*HW).
__device__ __forceinline__ float c2q(const float* __restrict__ hi, int b, int r, int k, int c,
                                     int sa, int sb, int HW) {
    int i2 = r >> 1, k2 = k >> 1;
    const float* p = hi + ((((b * HW) + i2) * HW + k2) * 36);
    int par = ((r & 1) << 1) | (k & 1);
    int off = (par == 1 || par == 2) ? 18 : 0;   // parities 1,2 use imag channels
    float va = __ldg(p + off + 3 * sa + c);
    float vb = __ldg(p + off + 3 * sb + c);
    float fa = (par == 3) ? -1.f : 1.f;          // par3: (re_b - re_a)
    float fb = (par == 2) ? -1.f : 1.f;          // par2: (im_a - im_b)
    return (fa * va + fb * vb) * SC;
}

__device__ __forceinline__ float conv7(const float* g, const float v[7]) {
    float a = 0.f;
#pragma unroll
    for (int j = 0; j < 7; j++) a += g[j] * v[6 - j];
    return a;
}

// ---------------- kernel 1: level-1 row colifilt ----------------
// low(8,256,256,3) + high1 subbands -> y1,y2 (8,512,256,3)
// each thread handles one q (4 output rows), fixed (b,w,c)
__global__ void k1_rows_l1(const float* __restrict__ low, const float* __restrict__ high1) {
    int idx = blockIdx.x * blockDim.x + threadIdx.x;
    const int TOT = 8 * 128 * 256 * 3;
    if (idx >= TOT) return;
    int c = idx % 3; int t = idx / 3;
    int w = t % 256; t /= 256;
    int q = t % 128; int b = t / 128;
    const int L = 256;

    float le[7], lo[7], lhe[7], lho[7], hle[7], hlo[7], hhe[7], hho[7];
#pragma unroll
    for (int j = 0; j < 7; j++) {
        int pe = refl(2 * (q + j) - 6, L);
        int po = refl(2 * (q + j) - 5, L);
        le[j]  = __ldg(low + (((b * 256) + pe) * 256 + w) * 3 + c);
        lo[j]  = __ldg(low + (((b * 256) + po) * 256 + w) * 3 + c);
        lhe[j] = c2q(high1, b, pe, w, c, 0, 5, 128);
        lho[j] = c2q(high1, b, po, w, c, 0, 5, 128);
        hle[j] = c2q(high1, b, pe, w, c, 2, 3, 128);
        hlo[j] = c2q(high1, b, po, w, c, 2, 3, 128);
        hhe[j] = c2q(high1, b, pe, w, c, 1, 4, 128);
        hho[j] = c2q(high1, b, po, w, c, 1, 4, 128);
    }
    float o1[4], o2[4];
    // lowband pair uses (G0B,G0A), sum>0 path: Xb=even, Xa=odd
    // highband pair uses (G1B,G1A), sum<0 path: Xb=odd,  Xa=even
    o1[0] = conv7(cG0B_E, le) + conv7(cG1B_E, lho);
    o1[1] = conv7(cG0A_E, lo) + conv7(cG1A_E, lhe);
    o1[2] = conv7(cG0B_O, le) + conv7(cG1B_O, lho);
    o1[3] = conv7(cG0A_O, lo) + conv7(cG1A_O, lhe);
    o2[0] = conv7(cG0B_E, hle) + conv7(cG1B_E, hho);
    o2[1] = conv7(cG0A_E, hlo) + conv7(cG1A_E, hhe);
    o2[2] = conv7(cG0B_O, hle) + conv7(cG1B_O, hho);
    o2[3] = conv7(cG0A_O, hlo) + conv7(cG1A_O, hhe);
#pragma unroll
    for (int s = 0; s < 4; s++) {
        int n = 4 * q + s;
        int oi = (((b * 512) + n) * 256 + w) * 3 + c;
        g_y1[oi] = o1[s];
        g_y2[oi] = o2[s];
    }
}

// ---------------- kernel 2: level-1 column colifilt ----------------
// y1,y2 (8,512,256,3) -> Z (8,512,512,3)
__global__ void k2_cols_l1() {
    int idx = blockIdx.x * blockDim.x + threadIdx.x;
    const int TOT = 8 * 512 * 128 * 3;
    if (idx >= TOT) return;
    int c = idx % 3; int t = idx / 3;
    int q = t % 128; t /= 128;
    int r = t % 512; int b = t / 512;
    const int L = 256;

    float e1[7], o1v[7], e2[7], o2v[7];
#pragma unroll
    for (int j = 0; j < 7; j++) {
        int pe = refl(2 * (q + j) - 6, L);
        int po = refl(2 * (q + j) - 5, L);
        int be = (((b * 512) + r) * 256 + pe) * 3 + c;
        int bo = (((b * 512) + r) * 256 + po) * 3 + c;
        e1[j]  = g_y1[be];  o1v[j] = g_y1[bo];
        e2[j]  = g_y2[be];  o2v[j] = g_y2[bo];
    }
    float o[4];
    o[0] = conv7(cG0B_E, e1)  + conv7(cG1B_E, o2v);
    o[1] = conv7(cG0A_E, o1v) + conv7(cG1A_E, e2);
    o[2] = conv7(cG0B_O, e1)  + conv7(cG1B_O, o2v);
    o[3] = conv7(cG0A_O, o1v) + conv7(cG1A_O, e2);
#pragma unroll
    for (int s = 0; s < 4; s++) {
        int n = 4 * q + s;
        g_Z[(((b * 512) + r) * 512 + n) * 3 + c] = o[s];
    }
}

// ---------------- kernel 3: level-0 row colfilter ----------------
// Z + high0 subbands -> t1,t2 (8,512,512,3)
__global__ void k3_rows_l0(const float* __restrict__ high0) {
    int idx = blockIdx.x * blockDim.x + threadIdx.x;
    const int TOT = 8 * 512 * 512 * 3;
    if (idx >= TOT) return;
    int c = idx % 3; int t = idx / 3;
    int k = t % 512; t /= 512;
    int i = t % 512; int b = t / 512;

    float a1 = 0.f, a2 = 0.f;
#pragma unroll
    for (int j = 0; j < 7; j++) {
        int r = refl(i + 3 - j, 512);
        a1 += cG0O[j] * g_Z[(((b * 512) + r) * 512 + k) * 3 + c];
        a2 += cG0O[j] * c2q(high0, b, r, k, c, 2, 3, 256);   // hl
    }
#pragma unroll
    for (int j = 0; j < 5; j++) {
        int r = refl(i + 2 - j, 512);
        a1 += cG1O[j] * c2q(high0, b, r, k, c, 0, 5, 256);   // lh
        a2 += cG1O[j] * c2q(high0, b, r, k, c, 1, 4, 256);   // hh
    }
    int oi = (((b * 512) + i) * 512 + k) * 3 + c;
    g_t1[oi] = a1;
    g_t2[oi] = a2;
}

// ---------------- kernel 4: level-0 column colfilter ----------------
// t1,t2 -> out (8,512,512,3)
__global__ void k4_cols_l0(float* __restrict__ out) {
    int idx = blockIdx.x * blockDim.x + threadIdx.x;
    const int TOT = 8 * 512 * 512 * 3;
    if (idx >= TOT) return;
    int c = idx % 3; int t = idx / 3;
    int k = t % 512; t /= 512;
    int i = t % 512; int b = t / 512;

    float a = 0.f;
    int rowbase = ((b * 512) + i) * 512;
#pragma unroll
    for (int j = 0; j < 7; j++) {
        int kk = refl(k + 3 - j, 512);
        a += cG0O[j] * g_t1[(rowbase + kk) * 3 + c];
    }
#pragma unroll
    for (int j = 0; j < 5; j++) {
        int kk = refl(k + 2 - j, 512);
        a += cG1O[j] * g_t2[(rowbase + kk) * 3 + c];
    }
    out[idx] = a;
}

// ---------------- launch ----------------
extern "C" void kernel_launch(void* const* d_in, const int* in_sizes, int n_in,
                              void* d_out, int out_size) {
    const float* low   = (const float*)d_in[0];
    const float* high0 = (const float*)d_in[1];
    const float* high1 = (const float*)d_in[2];
    float* out = (float*)d_out;

    const int T = 256;
    {
        int n = 8 * 128 * 256 * 3;
        k1_rows_l1<<<(n + T - 1) / T, T>>>(low, high1);
    }
    {
        int n = 8 * 512 * 128 * 3;
        k2_cols_l1<<<(n + T - 1) / T, T>>>();
    }
    {
        int n = 8 * 512 * 512 * 3;
        k3_rows_l0<<<(n + T - 1) / T, T>>>(high0);
    }
    {
        int n = 8 * 512 * 512 * 3;
        k4_cols_l0<<<(n + T - 1) / T, T>>>(out);
    }
}

// round 4
// speedup vs baseline: 1.2690x; 1.2690x over previous
#include <cuda_runtime.h>

#define SC 0.70710678118654752f

// ---------------- filter constants ----------------
__constant__ float cG0B_E[7] = { 0.00325314f,  0.03466035f, -0.11720389f,  0.75614564f,  0.01186609f,  0.02382538f, -0.00543948f};
__constant__ float cG0B_O[7] = {-0.00388321f, -0.03887280f,  0.27529538f,  0.56881042f, -0.10671180f,  0.01702522f, -0.00455690f};
__constant__ float cG0A_E[7] = {-0.00455690f,  0.01702522f, -0.10671180f,  0.56881042f,  0.27529538f, -0.03887280f, -0.00388321f};
__constant__ float cG0A_O[7] = {-0.00543948f,  0.02382538f,  0.01186609f,  0.75614564f, -0.11720389f,  0.03466035f,  0.00325314f};
__constant__ float cG1B_E[7] = {-0.00455690f,  0.01702522f, -0.10671180f,  0.56881042f,  0.27529538f, -0.03887280f, -0.00388321f};
__constant__ float cG1B_O[7] = { 0.00543948f, -0.02382538f, -0.01186609f, -0.75614564f,  0.11720389f, -0.03466035f, -0.00325314f};
__constant__ float cG1A_E[7] = {-0.00325314f, -0.03466035f,  0.11720389f, -0.75614564f, -0.01186609f, -0.02382538f,  0.00543948f};
__constant__ float cG1A_O[7] = {-0.00388321f, -0.03887280f,  0.27529538f,  0.56881042f, -0.10671180f,  0.01702522f, -0.00455690f};

__constant__ float cG0O[7] = {-0.0107142857142857f, -0.0535714285714286f, 0.2607142857142857f,
                               0.6071428571428571f,  0.2607142857142857f, -0.0535714285714286f,
                              -0.0107142857142857f};
__constant__ float cG1O[5] = {-0.05f, -0.25f, 0.6f, -0.25f, -0.05f};

// ---------------- planar scratch [c][b][H][W] ----------------
#define P256 (256*256)
#define P512x256 (512*256)
#define P512 (512*512)
__device__ float g_lowp[3*8*P256];
__device__ float g_LH1[3*8*P256];
__device__ float g_HL1[3*8*P256];
__device__ float g_HH1[3*8*P256];
__device__ float g_y1[3*8*P512x256];
__device__ float g_y2[3*8*P512x256];
__device__ float g_Z [3*8*P512];
__device__ float g_LH0[3*8*P512];
__device__ float g_HL0[3*8*P512];
__device__ float g_HH0[3*8*P512];
__device__ float g_t1[3*8*P512];
__device__ float g_t2[3*8*P512];

__device__ __forceinline__ int refl(int x, int L) {
    x = (x < 0) ? (-1 - x) : x;
    return (x >= L) ? (2 * L - 1 - x) : x;
}

// ---------------- kP: planarize low ----------------
// low (8,256,256,3) -> g_lowp [3][8][256][256]; 4 pixels per thread
__global__ void kP(const float* __restrict__ low) {
    int wt = threadIdx.x;         // 0..63
    int i  = blockIdx.x;          // 0..255
    int b  = blockIdx.y;          // 0..7
    const float4* p = reinterpret_cast<const float4*>(low + (((b * 256) + i) * 256 + 4 * wt) * 3);
    float4 v0 = __ldg(p), v1 = __ldg(p + 1), v2 = __ldg(p + 2);
    int o = i * 256 + 4 * wt;
    *reinterpret_cast<float4*>(g_lowp + (0 * 8 + b) * P256 + o) = make_float4(v0.x, v0.w, v1.z, v2.y);
    *reinterpret_cast<float4*>(g_lowp + (1 * 8 + b) * P256 + o) = make_float4(v0.y, v1.x, v1.w, v2.z);
    *reinterpret_cast<float4*>(g_lowp + (2 * 8 + b) * P256 + o) = make_float4(v0.z, v1.y, v2.x, v2.w);
}

// ---------------- c2q expansion ----------------
// write one quad (2x2) of one subband channel plane
__device__ __forceinline__ void c2q_store(float* plane, int W, int r0, int c0,
                                          float re_a, float im_a, float re_b, float im_b) {
    float pr  = (re_a + re_b) * SC;
    float pi  = (im_a + im_b) * SC;
    float qi  = (im_a - im_b) * SC;
    float nqr = (re_b - re_a) * SC;
    float* p = plane + r0 * W + c0;
    *reinterpret_cast<float2*>(p)     = make_float2(pr, pi);
    *reinterpret_cast<float2*>(p + W) = make_float2(qi, nqr);
}

// high0 (8,256,256,36) -> LH0,HL0,HH0 [3][8][512][512]
__global__ void kE0(const float* __restrict__ high0) {
    int k2 = threadIdx.x;   // 0..255
    int i2 = blockIdx.x;    // 0..255
    int b  = blockIdx.y;
    const float4* p4 = reinterpret_cast<const float4*>(high0 + (((b * 256) + i2) * 256 + k2) * 36);
    float v[36];
#pragma unroll
    for (int t = 0; t < 9; t++) {
        float4 f = __ldg(p4 + t);
        v[4 * t] = f.x; v[4 * t + 1] = f.y; v[4 * t + 2] = f.z; v[4 * t + 3] = f.w;
    }
    int r0 = 2 * i2, c0 = 2 * k2;
#pragma unroll
    for (int c = 0; c < 3; c++) {
        float* base = nullptr;
        // LH: pair(0,5)
        c2q_store(g_LH0 + (c * 8 + b) * P512, 512, r0, c0,
                  v[3 * 0 + c], v[18 + 3 * 0 + c], v[3 * 5 + c], v[18 + 3 * 5 + c]);
        // HL: pair(2,3)
        c2q_store(g_HL0 + (c * 8 + b) * P512, 512, r0, c0,
                  v[3 * 2 + c], v[18 + 3 * 2 + c], v[3 * 3 + c], v[18 + 3 * 3 + c]);
        // HH: pair(1,4)
        c2q_store(g_HH0 + (c * 8 + b) * P512, 512, r0, c0,
                  v[3 * 1 + c], v[18 + 3 * 1 + c], v[3 * 4 + c], v[18 + 3 * 4 + c]);
        (void)base;
    }
}

// high1 (8,128,128,36) -> LH1,HL1,HH1 [3][8][256][256]
__global__ void kE1(const float* __restrict__ high1) {
    int k2 = threadIdx.x;   // 0..127
    int i2 = blockIdx.x;    // 0..127
    int b  = blockIdx.y;
    const float4* p4 = reinterpret_cast<const float4*>(high1 + (((b * 128) + i2) * 128 + k2) * 36);
    float v[36];
#pragma unroll
    for (int t = 0; t < 9; t++) {
        float4 f = __ldg(p4 + t);
        v[4 * t] = f.x; v[4 * t + 1] = f.y; v[4 * t + 2] = f.z; v[4 * t + 3] = f.w;
    }
    int r0 = 2 * i2, c0 = 2 * k2;
#pragma unroll
    for (int c = 0; c < 3; c++) {
        c2q_store(g_LH1 + (c * 8 + b) * P256, 256, r0, c0,
                  v[3 * 0 + c], v[18 + 3 * 0 + c], v[3 * 5 + c], v[18 + 3 * 5 + c]);
        c2q_store(g_HL1 + (c * 8 + b) * P256, 256, r0, c0,
                  v[3 * 2 + c], v[18 + 3 * 2 + c], v[3 * 3 + c], v[18 + 3 * 3 + c]);
        c2q_store(g_HH1 + (c * 8 + b) * P256, 256, r0, c0,
                  v[3 * 1 + c], v[18 + 3 * 1 + c], v[3 * 4 + c], v[18 + 3 * 4 + c]);
    }
}

// ---------------- colifilt core: 14-sample window -> 4 outputs ----------------
// o0 = sum G0B_E[j]*L[12-2j] + G1B_E[j]*H[13-2j]
// o1 = sum G0A_E[j]*L[13-2j] + G1A_E[j]*H[12-2j]
// o2 = sum G0B_O[j]*L[12-2j] + G1B_O[j]*H[13-2j]
// o3 = sum G0A_O[j]*L[13-2j] + G1A_O[j]*H[12-2j]
__device__ __forceinline__ void colifilt4(const float L[14], const float H[14], float o[4]) {
    float a0 = 0.f, a1 = 0.f, a2 = 0.f, a3 = 0.f;
#pragma unroll
    for (int j = 0; j < 7; j++) {
        float le = L[12 - 2 * j], lo = L[13 - 2 * j];
        float he = H[12 - 2 * j], ho = H[13 - 2 * j];
        a0 += cG0B_E[j] * le + cG1B_E[j] * ho;
        a1 += cG0A_E[j] * lo + cG1A_E[j] * he;
        a2 += cG0B_O[j] * le + cG1B_O[j] * ho;
        a3 += cG0A_O[j] * lo + cG1A_O[j] * he;
    }
    o[0] = a0; o[1] = a1; o[2] = a2; o[3] = a3;
}

// ---------------- kA: level-1 row colifilt ----------------
// lowp+LH1 -> y1; HL1+HH1 -> y2 ; rows 256 -> 512
__global__ void kA() {
    int w  = threadIdx.x;   // 0..255
    int q  = blockIdx.x;    // 0..127
    int cb = blockIdx.y;    // 0..23
    int r0 = 2 * q - 6;
    bool interior = (q >= 3 && q <= 124);

    float L[14], H[14], o[4];
    // ---- y1 = colifilt(lowp) + colifilt(LH1) ----
    {
        const float* pl = g_lowp + cb * P256 + w;
        const float* ph = g_LH1  + cb * P256 + w;
        if (interior) {
            const float* a = pl + r0 * 256;
            const float* bp = ph + r0 * 256;
#pragma unroll
            for (int t = 0; t < 14; t++) { L[t] = __ldg(a + t * 256); H[t] = __ldg(bp + t * 256); }
        } else {
#pragma unroll
            for (int t = 0; t < 14; t++) {
                int rr = refl(r0 + t, 256) * 256;
                L[t] = __ldg(pl + rr); H[t] = __ldg(ph + rr);
            }
        }
        colifilt4(L, H, o);
        float* py = g_y1 + cb * P512x256 + (4 * q) * 256 + w;
        py[0] = o[0]; py[256] = o[1]; py[512] = o[2]; py[768] = o[3];
    }
    // ---- y2 = colifilt(HL1) + colifilt(HH1) ----
    {
        const float* pl = g_HL1 + cb * P256 + w;
        const float* ph = g_HH1 + cb * P256 + w;
        if (interior) {
            const float* a = pl + r0 * 256;
            const float* bp = ph + r0 * 256;
#pragma unroll
            for (int t = 0; t < 14; t++) { L[t] = __ldg(a + t * 256); H[t] = __ldg(bp + t * 256); }
        } else {
#pragma unroll
            for (int t = 0; t < 14; t++) {
                int rr = refl(r0 + t, 256) * 256;
                L[t] = __ldg(pl + rr); H[t] = __ldg(ph + rr);
            }
        }
        colifilt4(L, H, o);
        float* py = g_y2 + cb * P512x256 + (4 * q) * 256 + w;
        py[0] = o[0]; py[256] = o[1]; py[512] = o[2]; py[768] = o[3];
    }
}

// ---------------- kB: level-1 column colifilt ----------------
// y1,y2 (512x256) -> Z (512x512)
__global__ void kB() {
    int q  = threadIdx.x;   // 0..127
    int r  = blockIdx.x;    // 0..511
    int cb = blockIdx.y;    // 0..23
    int c0 = 2 * q - 6;
    const float* p1 = g_y1 + cb * P512x256 + r * 256;
    const float* p2 = g_y2 + cb * P512x256 + r * 256;
    float W1[14], W2[14], o[4];
    if (q >= 3 && q <= 124) {
        const float2* a = reinterpret_cast<const float2*>(p1 + c0);
        const float2* bp = reinterpret_cast<const float2*>(p2 + c0);
#pragma unroll
        for (int t = 0; t < 7; t++) {
            float2 u = __ldg(a + t);  W1[2 * t] = u.x; W1[2 * t + 1] = u.y;
            float2 v = __ldg(bp + t); W2[2 * t] = v.x; W2[2 * t + 1] = v.y;
        }
    } else {
#pragma unroll
        for (int t = 0; t < 14; t++) {
            int cc = refl(c0 + t, 256);
            W1[t] = __ldg(p1 + cc); W2[t] = __ldg(p2 + cc);
        }
    }
    colifilt4(W1, W2, o);
    *reinterpret_cast<float4*>(g_Z + cb * P512 + r * 512 + 4 * q) = make_float4(o[0], o[1], o[2], o[3]);
}

// ---------------- biort core: 10-sample g0 window + 8-sample g1 window -> 4 outputs ----------------
__device__ __forceinline__ void biort4(const float W0[10], const float W1[8], float o[4]) {
#pragma unroll
    for (int s = 0; s < 4; s++) {
        float a = 0.f;
#pragma unroll
        for (int j = 0; j < 7; j++) a += cG0O[j] * W0[s + 6 - j];
#pragma unroll
        for (int j = 0; j < 5; j++) a += cG1O[j] * W1[s + 4 - j];
        o[s] = a;
    }
}

// ---------------- kC: level-0 row colfilter ----------------
// t1 = colfilter(Z,g0)+colfilter(LH0,g1); t2 = colfilter(HL0,g0)+colfilter(HH0,g1)
__global__ void kC() {
    int w  = blockIdx.x * 256 + threadIdx.x;   // 0..511
    int it = blockIdx.y;                       // 0..127
    int cb = blockIdx.z;                       // 0..23
    int i0 = 4 * it;
    bool interior = (it >= 1 && it <= 126);
    float W0[10], W1[8], o[4];
    // ---- t1 ----
    {
        const float* pZ = g_Z   + cb * P512 + w;
        const float* pL = g_LH0 + cb * P512 + w;
        if (interior) {
            const float* a = pZ + (i0 - 3) * 512;
            const float* bp = pL + (i0 - 2) * 512;
#pragma unroll
            for (int t = 0; t < 10; t++) W0[t] = __ldg(a + t * 512);
#pragma unroll
            for (int t = 0; t < 8; t++)  W1[t] = __ldg(bp + t * 512);
        } else {
#pragma unroll
            for (int t = 0; t < 10; t++) W0[t] = __ldg(pZ + refl(i0 - 3 + t, 512) * 512);
#pragma unroll
            for (int t = 0; t < 8; t++)  W1[t] = __ldg(pL + refl(i0 - 2 + t, 512) * 512);
        }
        biort4(W0, W1, o);
        float* pt = g_t1 + cb * P512 + i0 * 512 + w;
        pt[0] = o[0]; pt[512] = o[1]; pt[1024] = o[2]; pt[1536] = o[3];
    }
    // ---- t2 ----
    {
        const float* pZ = g_HL0 + cb * P512 + w;
        const float* pL = g_HH0 + cb * P512 + w;
        if (interior) {
            const float* a = pZ + (i0 - 3) * 512;
            const float* bp = pL + (i0 - 2) * 512;
#pragma unroll
            for (int t = 0; t < 10; t++) W0[t] = __ldg(a + t * 512);
#pragma unroll
            for (int t = 0; t < 8; t++)  W1[t] = __ldg(bp + t * 512);
        } else {
#pragma unroll
            for (int t = 0; t < 10; t++) W0[t] = __ldg(pZ + refl(i0 - 3 + t, 512) * 512);
#pragma unroll
            for (int t = 0; t < 8; t++)  W1[t] = __ldg(pL + refl(i0 - 2 + t, 512) * 512);
        }
        biort4(W0, W1, o);
        float* pt = g_t2 + cb * P512 + i0 * 512 + w;
        pt[0] = o[0]; pt[512] = o[1]; pt[1024] = o[2]; pt[1536] = o[3];
    }
}

// ---------------- kD: level-0 column colfilter -> output ----------------
__global__ void kD(float* __restrict__ out) {
    int kt = threadIdx.x;     // 0..127
    int bi = blockIdx.x;      // 0..4095
    int b = bi >> 9, i = bi & 511;
    int k0 = 4 * kt;
    bool interior = (kt >= 1 && kt <= 126);
    float res[12];
    float W0[10], W1[8], o[4];
#pragma unroll
    for (int c = 0; c < 3; c++) {
        const float* p1 = g_t1 + (c * 8 + b) * P512 + i * 512;
        const float* p2 = g_t2 + (c * 8 + b) * P512 + i * 512;
        if (interior) {
#pragma unroll
            for (int t = 0; t < 10; t++) W0[t] = __ldg(p1 + k0 - 3 + t);
#pragma unroll
            for (int t = 0; t < 8; t++)  W1[t] = __ldg(p2 + k0 - 2 + t);
        } else {
#pragma unroll
            for (int t = 0; t < 10; t++) W0[t] = __ldg(p1 + refl(k0 - 3 + t, 512));
#pragma unroll
            for (int t = 0; t < 8; t++)  W1[t] = __ldg(p2 + refl(k0 - 2 + t, 512));
        }
        biort4(W0, W1, o);
        res[0 * 3 + c] = o[0]; res[1 * 3 + c] = o[1]; res[2 * 3 + c] = o[2]; res[3 * 3 + c] = o[3];
    }
    float4* po = reinterpret_cast<float4*>(out + (((b * 512) + i) * 512 + k0) * 3);
    po[0] = make_float4(res[0], res[1], res[2],  res[3]);
    po[1] = make_float4(res[4], res[5], res[6],  res[7]);
    po[2] = make_float4(res[8], res[9], res[10], res[11]);
}

// ---------------- launch ----------------
extern "C" void kernel_launch(void* const* d_in, const int* in_sizes, int n_in,
                              void* d_out, int out_size) {
    const float* low   = (const float*)d_in[0];
    const float* high0 = (const float*)d_in[1];
    const float* high1 = (const float*)d_in[2];
    float* out = (float*)d_out;

    kP <<<dim3(256, 8), 64>>>(low);
    kE1<<<dim3(128, 8), 128>>>(high1);
    kE0<<<dim3(256, 8), 256>>>(high0);
    kA <<<dim3(128, 24), 256>>>();
    kB <<<dim3(512, 24), 128>>>();
    kC <<<dim3(2, 128, 24), 256>>>();
    kD <<<4096, 128>>>(out);
}

// round 6
// speedup vs baseline: 1.5670x; 1.2348x over previous
#include <cuda_runtime.h>

#define SC 0.70710678118654752f

// ---------------- filter constants ----------------
__constant__ float cG0B_E[7] = { 0.00325314f,  0.03466035f, -0.11720389f,  0.75614564f,  0.01186609f,  0.02382538f, -0.00543948f};
__constant__ float cG0B_O[7] = {-0.00388321f, -0.03887280f,  0.27529538f,  0.56881042f, -0.10671180f,  0.01702522f, -0.00455690f};
__constant__ float cG0A_E[7] = {-0.00455690f,  0.01702522f, -0.10671180f,  0.56881042f,  0.27529538f, -0.03887280f, -0.00388321f};
__constant__ float cG0A_O[7] = {-0.00543948f,  0.02382538f,  0.01186609f,  0.75614564f, -0.11720389f,  0.03466035f,  0.00325314f};
__constant__ float cG1B_E[7] = {-0.00455690f,  0.01702522f, -0.10671180f,  0.56881042f,  0.27529538f, -0.03887280f, -0.00388321f};
__constant__ float cG1B_O[7] = { 0.00543948f, -0.02382538f, -0.01186609f, -0.75614564f,  0.11720389f, -0.03466035f, -0.00325314f};
__constant__ float cG1A_E[7] = {-0.00325314f, -0.03466035f,  0.11720389f, -0.75614564f, -0.01186609f, -0.02382538f,  0.00543948f};
__constant__ float cG1A_O[7] = {-0.00388321f, -0.03887280f,  0.27529538f,  0.56881042f, -0.10671180f,  0.01702522f, -0.00455690f};

__constant__ float cG0O[7] = {-0.0107142857142857f, -0.0535714285714286f, 0.2607142857142857f,
                               0.6071428571428571f,  0.2607142857142857f, -0.0535714285714286f,
                              -0.0107142857142857f};
__constant__ float cG1O[5] = {-0.05f, -0.25f, 0.6f, -0.25f, -0.05f};

// ---------------- planar scratch [c][b][H][W] ----------------
#define P256 (256*256)
#define P512 (512*512)
__device__ float g_lowp[3*8*P256];
__device__ float g_LH1[3*8*P256];
__device__ float g_HL1[3*8*P256];
__device__ float g_HH1[3*8*P256];
__device__ float g_Z [3*8*P512];
__device__ float g_LH0[3*8*P512];
__device__ float g_HL0[3*8*P512];
__device__ float g_HH0[3*8*P512];

__device__ __forceinline__ int refl(int x, int L) {
    x = (x < 0) ? (-1 - x) : x;
    return (x >= L) ? (2 * L - 1 - x) : x;
}

// ---------------- kP: planarize low ----------------
__global__ void kP(const float* __restrict__ low) {
    int wt = threadIdx.x;         // 0..63
    int i  = blockIdx.x;          // 0..255
    int b  = blockIdx.y;          // 0..7
    const float4* p = reinterpret_cast<const float4*>(low + (((b * 256) + i) * 256 + 4 * wt) * 3);
    float4 v0 = __ldg(p), v1 = __ldg(p + 1), v2 = __ldg(p + 2);
    int o = i * 256 + 4 * wt;
    *reinterpret_cast<float4*>(g_lowp + (0 * 8 + b) * P256 + o) = make_float4(v0.x, v0.w, v1.z, v2.y);
    *reinterpret_cast<float4*>(g_lowp + (1 * 8 + b) * P256 + o) = make_float4(v0.y, v1.x, v1.w, v2.z);
    *reinterpret_cast<float4*>(g_lowp + (2 * 8 + b) * P256 + o) = make_float4(v0.z, v1.y, v2.x, v2.w);
}

// ---------------- c2q expansion ----------------
__device__ __forceinline__ void c2q_store(float* plane, int W, int r0, int c0,
                                          float re_a, float im_a, float re_b, float im_b) {
    float pr  = (re_a + re_b) * SC;
    float pi  = (im_a + im_b) * SC;
    float qi  = (im_a - im_b) * SC;
    float nqr = (re_b - re_a) * SC;
    float* p = plane + r0 * W + c0;
    *reinterpret_cast<float2*>(p)     = make_float2(pr, pi);
    *reinterpret_cast<float2*>(p + W) = make_float2(qi, nqr);
}

__global__ void kE0(const float* __restrict__ high0) {
    int k2 = threadIdx.x;   // 0..255
    int i2 = blockIdx.x;    // 0..255
    int b  = blockIdx.y;
    const float4* p4 = reinterpret_cast<const float4*>(high0 + (((b * 256) + i2) * 256 + k2) * 36);
    float v[36];
#pragma unroll
    for (int t = 0; t < 9; t++) {
        float4 f = __ldg(p4 + t);
        v[4 * t] = f.x; v[4 * t + 1] = f.y; v[4 * t + 2] = f.z; v[4 * t + 3] = f.w;
    }
    int r0 = 2 * i2, c0 = 2 * k2;
#pragma unroll
    for (int c = 0; c < 3; c++) {
        c2q_store(g_LH0 + (c * 8 + b) * P512, 512, r0, c0,
                  v[c], v[18 + c], v[15 + c], v[33 + c]);
        c2q_store(g_HL0 + (c * 8 + b) * P512, 512, r0, c0,
                  v[6 + c], v[24 + c], v[9 + c], v[27 + c]);
        c2q_store(g_HH0 + (c * 8 + b) * P512, 512, r0, c0,
                  v[3 + c], v[21 + c], v[12 + c], v[30 + c]);
    }
}

__global__ void kE1(const float* __restrict__ high1) {
    int k2 = threadIdx.x;   // 0..127
    int i2 = blockIdx.x;    // 0..127
    int b  = blockIdx.y;
    const float4* p4 = reinterpret_cast<const float4*>(high1 + (((b * 128) + i2) * 128 + k2) * 36);
    float v[36];
#pragma unroll
    for (int t = 0; t < 9; t++) {
        float4 f = __ldg(p4 + t);
        v[4 * t] = f.x; v[4 * t + 1] = f.y; v[4 * t + 2] = f.z; v[4 * t + 3] = f.w;
    }
    int r0 = 2 * i2, c0 = 2 * k2;
#pragma unroll
    for (int c = 0; c < 3; c++) {
        c2q_store(g_LH1 + (c * 8 + b) * P256, 256, r0, c0,
                  v[c], v[18 + c], v[15 + c], v[33 + c]);
        c2q_store(g_HL1 + (c * 8 + b) * P256, 256, r0, c0,
                  v[6 + c], v[24 + c], v[9 + c], v[27 + c]);
        c2q_store(g_HH1 + (c * 8 + b) * P256, 256, r0, c0,
                  v[3 + c], v[21 + c], v[12 + c], v[30 + c]);
    }
}

// ---------------- colifilt core ----------------
__device__ __forceinline__ void colifilt4(const float L[14], const float H[14], float o[4]) {
    float a0 = 0.f, a1 = 0.f, a2 = 0.f, a3 = 0.f;
#pragma unroll
    for (int j = 0; j < 7; j++) {
        float le = L[12 - 2 * j], lo = L[13 - 2 * j];
        float he = H[12 - 2 * j], ho = H[13 - 2 * j];
        a0 += cG0B_E[j] * le + cG1B_E[j] * ho;
        a1 += cG0A_E[j] * lo + cG1A_E[j] * he;
        a2 += cG0B_O[j] * le + cG1B_O[j] * ho;
        a3 += cG0A_O[j] * lo + cG1A_O[j] * he;
    }
    o[0] = a0; o[1] = a1; o[2] = a2; o[3] = a3;
}

// ---------------- biort core ----------------
__device__ __forceinline__ void biort4(const float W0[10], const float W1[8], float o[4]) {
#pragma unroll
    for (int s = 0; s < 4; s++) {
        float a = 0.f;
#pragma unroll
        for (int j = 0; j < 7; j++) a += cG0O[j] * W0[s + 6 - j];
#pragma unroll
        for (int j = 0; j < 5; j++) a += cG1O[j] * W1[s + 4 - j];
        o[s] = a;
    }
}

// ---------------- kF1: fused level-1 (rows then cols) ----------------
// Block: (q, cb). Phase 1: row colifilt -> smem y strip (4 rows x 256).
// Phase 2: column colifilt from smem -> Z rows 4q..4q+3 (512 wide).
__global__ void kF1() {
    __shared__ float sy1[4][256];
    __shared__ float sy2[4][256];
    int w  = threadIdx.x;   // 0..255
    int q  = blockIdx.x;    // 0..127
    int cb = blockIdx.y;    // 0..23
    int r0 = 2 * q - 6;
    bool interior = (q >= 3 && q <= 124);

    float L[14], H[14], o[4];
    // ---- y1 = colifilt(lowp, G0) + colifilt(LH1, G1) ----
    {
        const float* pl = g_lowp + cb * P256 + w;
        const float* ph = g_LH1  + cb * P256 + w;
        if (interior) {
#pragma unroll
            for (int t = 0; t < 14; t++) { L[t] = __ldg(pl + (r0 + t) * 256); H[t] = __ldg(ph + (r0 + t) * 256); }
        } else {
#pragma unroll
            for (int t = 0; t < 14; t++) {
                int rr = refl(r0 + t, 256) * 256;
                L[t] = __ldg(pl + rr); H[t] = __ldg(ph + rr);
            }
        }
        colifilt4(L, H, o);
        sy1[0][w] = o[0]; sy1[1][w] = o[1]; sy1[2][w] = o[2]; sy1[3][w] = o[3];
    }
    // ---- y2 = colifilt(HL1, G0) + colifilt(HH1, G1) ----
    {
        const float* pl = g_HL1 + cb * P256 + w;
        const float* ph = g_HH1 + cb * P256 + w;
        if (interior) {
#pragma unroll
            for (int t = 0; t < 14; t++) { L[t] = __ldg(pl + (r0 + t) * 256); H[t] = __ldg(ph + (r0 + t) * 256); }
        } else {
#pragma unroll
            for (int t = 0; t < 14; t++) {
                int rr = refl(r0 + t, 256) * 256;
                L[t] = __ldg(pl + rr); H[t] = __ldg(ph + rr);
            }
        }
        colifilt4(L, H, o);
        sy2[0][w] = o[0]; sy2[1][w] = o[1]; sy2[2][w] = o[2]; sy2[3][w] = o[3];
    }
    __syncthreads();
    // ---- phase 2: column colifilt ----
    float* zb = g_Z + cb * P512 + (4 * q) * 512;
#pragma unroll
    for (int rep = 0; rep < 2; rep++) {
        int task = threadIdx.x + rep * 256;   // 0..511
        int s = task >> 7, qc = task & 127;
        int c0 = 2 * qc - 6;
        float W1[14], W2[14];
        if (qc >= 3 && qc <= 124) {
#pragma unroll
            for (int t = 0; t < 14; t++) { W1[t] = sy1[s][c0 + t]; W2[t] = sy2[s][c0 + t]; }
        } else {
#pragma unroll
            for (int t = 0; t < 14; t++) {
                int cc = refl(c0 + t, 256);
                W1[t] = sy1[s][cc]; W2[t] = sy2[s][cc];
            }
        }
        colifilt4(W1, W2, o);
        *reinterpret_cast<float4*>(zb + s * 512 + 4 * qc) = make_float4(o[0], o[1], o[2], o[3]);
    }
}

// ---------------- kF2: fused level-0 (rows then cols) -> output ----------------
// Block: (it, b), all 3 channels. Phase 1: row biort -> smem t strips (3ch x 4 rows x 512).
// Phase 2: column biort from smem -> out rows 4it..4it+3.
__global__ void kF2(float* __restrict__ out) {
    __shared__ float st1[3][4][512];
    __shared__ float st2[3][4][512];
    int it = blockIdx.x;    // 0..127
    int b  = blockIdx.y;    // 0..7
    int i0 = 4 * it;
    bool interior = (it >= 1 && it <= 126);
    float W0[10], W1[8], o[4];

#pragma unroll
    for (int c = 0; c < 3; c++) {
        int pb = c * 8 + b;
#pragma unroll
        for (int rep = 0; rep < 2; rep++) {
            int w = threadIdx.x + rep * 256;  // 0..511
            // t1 = colfilter(Z,g0) + colfilter(LH0,g1)
            {
                const float* pZ = g_Z   + pb * P512 + w;
                const float* pL = g_LH0 + pb * P512 + w;
                if (interior) {
#pragma unroll
                    for (int t = 0; t < 10; t++) W0[t] = __ldg(pZ + (i0 - 3 + t) * 512);
#pragma unroll
                    for (int t = 0; t < 8; t++)  W1[t] = __ldg(pL + (i0 - 2 + t) * 512);
                } else {
#pragma unroll
                    for (int t = 0; t < 10; t++) W0[t] = __ldg(pZ + refl(i0 - 3 + t, 512) * 512);
#pragma unroll
                    for (int t = 0; t < 8; t++)  W1[t] = __ldg(pL + refl(i0 - 2 + t, 512) * 512);
                }
                biort4(W0, W1, o);
                st1[c][0][w] = o[0]; st1[c][1][w] = o[1]; st1[c][2][w] = o[2]; st1[c][3][w] = o[3];
            }
            // t2 = colfilter(HL0,g0) + colfilter(HH0,g1)
            {
                const float* pZ = g_HL0 + pb * P512 + w;
                const float* pL = g_HH0 + pb * P512 + w;
                if (interior) {
#pragma unroll
                    for (int t = 0; t < 10; t++) W0[t] = __ldg(pZ + (i0 - 3 + t) * 512);
#pragma unroll
                    for (int t = 0; t < 8; t++)  W1[t] = __ldg(pL + (i0 - 2 + t) * 512);
                } else {
#pragma unroll
                    for (int t = 0; t < 10; t++) W0[t] = __ldg(pZ + refl(i0 - 3 + t, 512) * 512);
#pragma unroll
                    for (int t = 0; t < 8; t++)  W1[t] = __ldg(pL + refl(i0 - 2 + t, 512) * 512);
                }
                biort4(W0, W1, o);
                st2[c][0][w] = o[0]; st2[c][1][w] = o[1]; st2[c][2][w] = o[2]; st2[c][3][w] = o[3];
            }
        }
    }
    __syncthreads();
    // ---- phase 2: column biort ----
#pragma unroll
    for (int rep = 0; rep < 2; rep++) {
        int task = threadIdx.x + rep * 256;   // 0..511
        int s = task >> 7, kg = task & 127;
        int k0 = 4 * kg;
        float res[12];
        if (kg >= 1 && kg <= 126) {
#pragma unroll
            for (int c = 0; c < 3; c++) {
                const float4* p1 = reinterpret_cast<const float4*>(&st1[c][s][k0 - 4]);
                const float4* p2 = reinterpret_cast<const float4*>(&st2[c][s][k0 - 4]);
                float4 a0 = p1[0], a1 = p1[1], a2 = p1[2];
                float4 b0 = p2[0], b1 = p2[1], b2 = p2[2];
                float V0[12] = {a0.x,a0.y,a0.z,a0.w, a1.x,a1.y,a1.z,a1.w, a2.x,a2.y,a2.z,a2.w};
                float V1[12] = {b0.x,b0.y,b0.z,b0.w, b1.x,b1.y,b1.z,b1.w, b2.x,b2.y,b2.z,b2.w};
                biort4(&V0[1], &V1[2], o);
                res[c] = o[0]; res[3 + c] = o[1]; res[6 + c] = o[2]; res[9 + c] = o[3];
            }
        } else {
#pragma unroll
            for (int c = 0; c < 3; c++) {
                const float* p1 = st1[c][s];
                const float* p2 = st2[c][s];
#pragma unroll
                for (int t = 0; t < 10; t++) W0[t] = p1[refl(k0 - 3 + t, 512)];
#pragma unroll
                for (int t = 0; t < 8; t++)  W1[t] = p2[refl(k0 - 2 + t, 512)];
                biort4(W0, W1, o);
                res[c] = o[0]; res[3 + c] = o[1]; res[6 + c] = o[2]; res[9 + c] = o[3];
            }
        }
        float4* po = reinterpret_cast<float4*>(out + (((b * 512) + (i0 + s)) * 512 + k0) * 3);
        po[0] = make_float4(res[0], res[1], res[2],  res[3]);
        po[1] = make_float4(res[4], res[5], res[6],  res[7]);
        po[2] = make_float4(res[8], res[9], res[10], res[11]);
    }
}

// ---------------- launch ----------------
extern "C" void kernel_launch(void* const* d_in, const int* in_sizes, int n_in,
                              void* d_out, int out_size) {
    const float* low   = (const float*)d_in[0];
    const float* high0 = (const float*)d_in[1];
    const float* high1 = (const float*)d_in[2];
    float* out = (float*)d_out;

    kP <<<dim3(256, 8), 64>>>(low);
    kE1<<<dim3(128, 8), 128>>>(high1);
    kE0<<<dim3(256, 8), 256>>>(high0);
    kF1<<<dim3(128, 24), 256>>>();
    kF2<<<dim3(128, 8), 256>>>(out);
}